// round 4
// baseline (speedup 1.0000x reference)
#include <cuda_runtime.h>

#define NB 64
#define NT 256
#define BT (NB*NT)
#define TBL 16
#define BNS 0.9999950000374997f

__constant__ int c_s2j[25] = {0,1,2,3,20, 4,5,6,7,21,22, 8,9,10,11,23,24, 12,13,14,15, 16,17,18,19};
__constant__ int c_gstart[5] = {0,5,11,17,21};
__constant__ int c_gn[5]     = {5,6,6,4,4};

__device__ float g_adj[5][6][6];
__device__ float g_H [BT*25*64];
__device__ float g_Z [BT*25*128];
__device__ float g_Y1[BT*25*64];
__device__ float g_Y2[BT*25*128];
__device__ float g_Y3[BT*25*64];
__device__ float g_feat[5*64*64];
__device__ float g_loss[5*64];
__device__ float g_sw1[5*64*64],  g_sb1[5*64];
__device__ float g_sw2[5*128*64], g_sb2[5*128];
__device__ float g_sw3[5*64*128], g_sb3[5*64];
__device__ float g_rw2[5*128*64], g_rw3[5*64*128];
__device__ float g_cst2[5*128],   g_cst3[5*64];
__device__ float g_tw1[5*3*64*64], g_tw2[5*3*128*128], g_tw3[5*3*64*64];

__global__ __launch_bounds__(256) void k_prep(
    const float* __restrict__ sw1, const float* __restrict__ sb1,
    const float* __restrict__ tw1,
    const float* __restrict__ rw2, const float* __restrict__ rb2,
    const float* __restrict__ rg2, const float* __restrict__ rbb2,
    const float* __restrict__ sw2, const float* __restrict__ sb2,
    const float* __restrict__ tw2, const float* __restrict__ tb2,
    const float* __restrict__ rw3, const float* __restrict__ rb3,
    const float* __restrict__ rg3, const float* __restrict__ rbb3,
    const float* __restrict__ sw3, const float* __restrict__ sb3,
    const float* __restrict__ tw3, const float* __restrict__ tb3)
{
    int gt  = blockIdx.x*blockDim.x + threadIdx.x;
    int NTH = gridDim.x*blockDim.x;
    for (int i=gt;i<5*64*64;i+=NTH){
        int g=i/4096, r=i%4096, o=r/64, c=r%64;
        const float* w = sw1 + g*192*64;
        g_sw1[i] = w[o*64+c] + w[(64+o)*64+c] + w[(128+o)*64+c];
    }
    for (int i=gt;i<5*128*64;i+=NTH){
        int g=i/8192, r=i%8192, o=r/64, c=r%64;
        const float* w = sw2 + g*384*64;
        g_sw2[i] = w[o*64+c] + w[(128+o)*64+c] + w[(256+o)*64+c];
    }
    for (int i=gt;i<5*64*128;i+=NTH){
        int g=i/8192, r=i%8192, o=r/128, c=r%128;
        const float* w = sw3 + g*192*128;
        g_sw3[i] = w[o*128+c] + w[(64+o)*128+c] + w[(128+o)*128+c];
    }
    for (int i=gt;i<5*128*64;i+=NTH){
        int g=i/8192, o=(i%8192)/64;
        g_rw2[i] = rw2[i] * rg2[g*128+o] * BNS;
    }
    for (int i=gt;i<5*64*128;i+=NTH){
        int g=i/8192, o=(i%8192)/128;
        g_rw3[i] = rw3[i] * rg3[g*64+o] * BNS;
    }
    // transpose temporal conv weights: [g][o][c][kt] -> [g][kt][o][c]
    for (int i=gt;i<5*3*64*64;i+=NTH){
        int c=i%64, o=(i/64)%64, kt=(i/4096)%3, g=i/12288;
        g_tw1[i] = tw1[((g*64+o)*64+c)*3+kt];
        g_tw3[i] = tw3[((g*64+o)*64+c)*3+kt];
    }
    for (int i=gt;i<5*3*128*128;i+=NTH){
        int c=i%128, o=(i/128)%128, kt=(i/16384)%3, g=i/49152;
        g_tw2[i] = tw2[((g*128+o)*128+c)*3+kt];
    }
    for (int i=gt;i<5*64;i+=NTH){
        int g=i/64, o=i%64;
        const float* s1 = sb1 + g*192;
        g_sb1[i]  = s1[o] + s1[64+o] + s1[128+o];
        const float* s3 = sb3 + g*192;
        g_sb3[i]  = s3[o] + s3[64+o] + s3[128+o];
        g_cst3[i] = tb3[i] + rb3[i]*rg3[i]*BNS + rbb3[i];
    }
    for (int i=gt;i<5*128;i+=NTH){
        int g=i/128, o=i%128;
        const float* s = sb2 + g*384;
        g_sb2[i]  = s[o] + s[128+o] + s[256+o];
        g_cst2[i] = tb2[i] + rb2[i]*rg2[i]*BNS + rbb2[i];
    }
    if (gt==0){
        double fa[25][25];
        for (int i=0;i<25;i++) for (int j=0;j<25;j++) fa[i][j]=0.0;
        const int E[24][2]={{3,2},{2,20},{20,1},{1,0},{20,4},{4,5},{5,6},{6,22},
                            {6,7},{7,21},{20,8},{8,9},{9,10},{10,24},{10,11},{11,23},
                            {0,12},{12,13},{13,14},{14,15},{0,16},{16,17},{17,18},{18,19}};
        for (int k=0;k<24;k++){
            int i=E[k][0]-1, j=E[k][1]-1;
            fa[i][j]=1.0; fa[j][i]=1.0;
        }
        for (int i=0;i<25;i++) fa[i][i]+=1.0;
        for (int i=0;i<25;i++){
            double d=0; for (int j=0;j<25;j++) d+=fa[i][j];
            if (d==0.0) d=1.0;
            for (int j=0;j<25;j++) fa[i][j]/=d;
        }
        for (int g=0;g<5;g++){
            int n=c_gn[g];
            int js[6]; for (int u=0;u<n;u++) js[u]=c_s2j[c_gstart[g]+u];
            double sa[6][6];
            for (int u=0;u<n;u++) for (int v=0;v<n;v++) sa[u][v]=fa[js[u]][js[v]];
            for (int u=0;u<n;u++) sa[u][u]+=1.0;
            double dg[6];
            for (int u=0;u<n;u++){ double d=0; for (int v=0;v<n;v++) d+=sa[u][v]; dg[u]=d; }
            for (int node=1;node<n;node++)
                if (dg[node]==1.0){ sa[0][node]=1.0; sa[node][0]=1.0; }
            for (int u=0;u<6;u++) for (int v=0;v<6;v++){
                float val=0.f;
                if (u<n && v<n){
                    double d=0; for (int w=0;w<n;w++) d+=sa[u][w];
                    if (d==0.0) d=1.0;
                    val=(float)(sa[u][v]/d);
                }
                g_adj[g][u][v]=val;
            }
        }
    }
}

__global__ __launch_bounds__(256) void k_embed(const float* __restrict__ x,
                                               const float* __restrict__ ew,
                                               const float* __restrict__ eb)
{
    int idx = blockIdx.x*256 + threadIdx.x;
    int c   = idx & 63;
    int row = idx >> 6;
    int s   = row % 25;
    int bt  = row / 25;
    int j   = c_s2j[s];
    const float* xp = x + (bt*25 + j)*3;
    g_H[idx] = eb[c] + xp[0]*ew[c*3+0] + xp[1]*ew[c*3+1] + xp[2]*ew[c*3+2];
}

// dot4 with ascending-k accumulation order
__device__ __forceinline__ void dot4(float4& acc, float4 a, float4 w0, float4 w1, float4 w2, float4 w3){
    acc.x = fmaf(a.w,w0.w, fmaf(a.z,w0.z, fmaf(a.y,w0.y, fmaf(a.x,w0.x, acc.x))));
    acc.y = fmaf(a.w,w1.w, fmaf(a.z,w1.z, fmaf(a.y,w1.y, fmaf(a.x,w1.x, acc.y))));
    acc.z = fmaf(a.w,w2.w, fmaf(a.z,w2.z, fmaf(a.y,w2.y, fmaf(a.x,w2.x, acc.z))));
    acc.w = fmaf(a.w,w3.w, fmaf(a.z,w3.z, fmaf(a.y,w3.y, fmaf(a.x,w3.x, acc.w))));
}

// stage one 32-k chunk of W (row-major [o][cin], row stride CINW) into
// sW4[kk4][COUT+1]; entry (kk4,o) = {W[o][k0+4*kk4 + 0..3]}
template<int COUT>
__device__ __forceinline__ void stageW(float4* sW4, const float* __restrict__ Wg,
                                       int CINW, int k0, int tid, int TH)
{
    for (int p = tid; p < COUT*8; p += TH){
        int o = p >> 3, kk4 = p & 7;
        const float* wp = Wg + o*CINW + k0 + kk4*4;
        sW4[kk4*(COUT+1) + o] = *(const float4*)wp;
    }
}

template<int CIN,int COUT>
__global__ __launch_bounds__((COUT/4)*16) void k_gcn(const float* __restrict__ Y,
                                                     float* __restrict__ Z,
                                                     const float* __restrict__ W,
                                                     const float* __restrict__ Bv)
{
    constexpr int CT = COUT/4;
    constexpr int TH = CT*16;
    extern __shared__ float sm[];
    float*  sA  = sm;                         // [96][CIN]
    float4* sW4 = (float4*)(sm + 96*CIN);     // [8][COUT+1]
    __shared__ float sAdj[6][6];

    const int g   = blockIdx.y;
    const int n   = c_gn[g];
    const int gs0 = c_gstart[g];
    const int bt0 = blockIdx.x * TBL;
    const int tid = threadIdx.x;
    if (tid < 36) sAdj[tid/6][tid%6] = g_adj[g][tid/6][tid%6];
    __syncthreads();

    constexpr int C4 = CIN/4;
    for (int p=tid; p<96*C4; p+=TH){
        int c4 = p % C4, r = p / C4, u = r % 6, t = r / 6;
        float4 acc = make_float4(0.f,0.f,0.f,0.f);
        if (u < n){
            const float4* yp = (const float4*)(Y + ((size_t)(bt0+t)*25 + gs0)*CIN) + c4;
            #pragma unroll
            for (int v=0; v<6; ++v)
                if (v < n){
                    float av = sAdj[u][v];
                    float4 yv = yp[(size_t)v*C4];
                    acc.x += av*yv.x; acc.y += av*yv.y; acc.z += av*yv.z; acc.w += av*yv.w;
                }
        }
        ((float4*)sA)[p] = acc;
    }

    const int ty = tid / CT, tx = tid % CT;
    float4 acc[6];
    {
        float4 b4 = *(const float4*)(Bv + g*COUT + tx*4);
        #pragma unroll
        for (int i=0;i<6;++i) acc[i]=b4;
    }
    const float* Wg = W + g*COUT*CIN;

    for (int k0=0;k0<CIN;k0+=32){
        __syncthreads();
        stageW<COUT>(sW4, Wg, CIN, k0, tid, TH);
        __syncthreads();
        #pragma unroll
        for (int kk4=0;kk4<8;++kk4){
            const float4* wb = sW4 + kk4*(COUT+1) + 4*tx;
            float4 w0=wb[0], w1=wb[1], w2=wb[2], w3=wb[3];
            #pragma unroll
            for (int i=0;i<6;++i){
                float4 a = *(const float4*)(sA + (ty+16*i)*CIN + k0 + kk4*4);
                dot4(acc[i], a, w0,w1,w2,w3);
            }
        }
    }
    #pragma unroll
    for (int i=0;i<6;++i){
        int r = ty+16*i, t = r/6, u = r%6;
        if (u < n)
            *(float4*)(Z + ((size_t)(bt0+t)*25 + gs0+u)*COUT + tx*4) = acc[i];
    }
}

template<int CIN,int COUT,int CRES,int MODE>
__global__ __launch_bounds__((COUT/4)*16) void k_tconv(const float* __restrict__ Zin,
                                                       const float* __restrict__ Yres,
                                                       float* __restrict__ Yout,
                                                       const float* __restrict__ TWt,
                                                       const float* __restrict__ RW,
                                                       const float* __restrict__ CST,
                                                       const float* __restrict__ GS,
                                                       const float* __restrict__ BB)
{
    constexpr int CT = COUT/4;
    constexpr int TH = CT*16;
    constexpr int SZSZ = (TBL+2)*6*CIN;
    constexpr int SRSZ = TBL*6*CRES;
    constexpr int SBUF = (SZSZ > SRSZ ? SZSZ : SRSZ);
    extern __shared__ float sm[];
    float*  sB  = sm;
    float4* sW4 = (float4*)(sm + SBUF);       // [8][COUT+1]

    const int g   = blockIdx.y;
    const int n   = c_gn[g];
    const int gs0 = c_gstart[g];
    const int bt0 = blockIdx.x * TBL;
    const int t0  = bt0 & (NT-1);
    const int tid = threadIdx.x, ty = tid/CT, tx = tid%CT;

    constexpr int C4 = CIN/4;
    for (int p=tid; p<(TBL+2)*6*C4; p+=TH){
        int c4 = p % C4, r = p / C4, u = r % 6, hb = r / 6;
        int t = t0 + hb - 1;
        float4 v = make_float4(0.f,0.f,0.f,0.f);
        if (u < n && t >= 0 && t < NT)
            v = ((const float4*)(Zin + ((size_t)(bt0+hb-1)*25 + gs0+u)*CIN))[c4];
        ((float4*)sB)[p] = v;
    }

    float4 acc[6];
    #pragma unroll
    for (int i=0;i<6;++i) acc[i]=make_float4(0.f,0.f,0.f,0.f);

    const float* TWg = TWt + g*3*COUT*CIN;
    for (int kt=0;kt<3;++kt){
        for (int k0=0;k0<CIN;k0+=32){
            __syncthreads();
            stageW<COUT>(sW4, TWg + kt*COUT*CIN, CIN, k0, tid, TH);
            __syncthreads();
            #pragma unroll
            for (int kk4=0;kk4<8;++kk4){
                const float4* wb = sW4 + kk4*(COUT+1) + 4*tx;
                float4 w0=wb[0], w1=wb[1], w2=wb[2], w3=wb[3];
                #pragma unroll
                for (int i=0;i<6;++i){
                    float4 a = *(const float4*)(sB + (ty+16*i + 6*kt)*CIN + k0 + kk4*4);
                    dot4(acc[i], a, w0,w1,w2,w3);
                }
            }
        }
    }

    if (MODE==1){
        __syncthreads();
        constexpr int R4 = CRES/4;
        for (int p=tid; p<TBL*6*R4; p+=TH){
            int c4 = p % R4, r = p / R4, u = r % 6, t = r / 6;
            float4 v = make_float4(0.f,0.f,0.f,0.f);
            if (u < n)
                v = ((const float4*)(Yres + ((size_t)(bt0+t)*25 + gs0+u)*CRES))[c4];
            ((float4*)sB)[p] = v;
        }
        const float* RWg = RW + g*COUT*CRES;
        for (int k0=0;k0<CRES;k0+=32){
            __syncthreads();
            stageW<COUT>(sW4, RWg, CRES, k0, tid, TH);
            __syncthreads();
            #pragma unroll
            for (int kk4=0;kk4<8;++kk4){
                const float4* wb = sW4 + kk4*(COUT+1) + 4*tx;
                float4 w0=wb[0], w1=wb[1], w2=wb[2], w3=wb[3];
                #pragma unroll
                for (int i=0;i<6;++i){
                    float4 a = *(const float4*)(sB + (ty+16*i)*CRES + k0 + kk4*4);
                    dot4(acc[i], a, w0,w1,w2,w3);
                }
            }
        }
    }

    float4 cst = *(const float4*)(CST + g*COUT + tx*4);
    float4 gs  = *(const float4*)(GS  + g*COUT + tx*4);
    float4 bb  = *(const float4*)(BB  + g*COUT + tx*4);
    gs.x*=BNS; gs.y*=BNS; gs.z*=BNS; gs.w*=BNS;
    #pragma unroll
    for (int i=0;i<6;++i){
        int r = ty+16*i, t = r/6, u = r%6;
        if (u < n){
            size_t rowoff = (size_t)(bt0+t)*25 + gs0+u;
            float4 pre = acc[i];
            pre.x += cst.x; pre.y += cst.y; pre.z += cst.z; pre.w += cst.w;
            if (MODE==0){
                float4 rr = *(const float4*)(Yres + rowoff*COUT + tx*4);
                pre.x += rr.x; pre.y += rr.y; pre.z += rr.z; pre.w += rr.w;
            }
            float4 o;
            o.x = fmaxf(pre.x*gs.x + bb.x, 0.f);
            o.y = fmaxf(pre.y*gs.y + bb.y, 0.f);
            o.z = fmaxf(pre.z*gs.z + bb.z, 0.f);
            o.w = fmaxf(pre.w*gs.w + bb.w, 0.f);
            *(float4*)(Yout + rowoff*COUT + tx*4) = o;
        }
    }
}

__global__ __launch_bounds__(256) void k_feat()
{
    int g = blockIdx.x, b = blockIdx.y;
    int tid = threadIdx.x;
    int o = tid & 63, part = tid >> 6;
    int n = c_gn[g], gs0 = c_gstart[g];
    float s = 0.f;
    int total = NT*n;
    for (int q=part; q<total; q+=4){
        int t = q / n, u = q % n;
        s += g_Y3[((size_t)(b*NT+t)*25 + gs0+u)*64 + o];
    }
    __shared__ float red[256];
    red[tid]=s; __syncthreads();
    if (part==0)
        g_feat[(g*64+b)*64 + o] = (red[o]+red[64+o]+red[128+o]+red[192+o]) / (float)(NT*n);
}

__global__ __launch_bounds__(128) void k_vq(const float* __restrict__ cb,
                                            float* __restrict__ out)
{
    int g = blockIdx.x, b = blockIdx.y;
    int k = threadIdx.x;
    const float* f   = g_feat + (g*64+b)*64;
    const float* ck  = cb + (g*128 + k)*64;
    float dot=0.f, scb=0.f;
    for (int o=0;o<64;++o){ dot += f[o]*ck[o]; scb += ck[o]*ck[o]; }
    float d = scb - 2.f*dot;

    __shared__ float ds[128];
    __shared__ int   sidx;
    ds[k]=d; __syncthreads();
    if (k==0){
        float best = ds[0]; int bi = 0;
        for (int kk=1;kk<128;++kk) if (ds[kk] < best){ best = ds[kk]; bi = kk; }
        sidx = bi;
    }
    __syncthreads();
    int idx = sidx;
    const float* cq = cb + (g*128 + idx)*64;
    __shared__ float dsq[64];
    if (k < 64){
        float q = cq[k];
        out[(g*64+b)*64 + k] = q;
        float dd = q - f[k];
        dsq[k] = dd*dd;
    }
    __syncthreads();
    if (k==0){
        float s=0.f;
        for (int o=0;o<64;++o) s += dsq[o];
        g_loss[g*64+b] = 1.25f * s / 4096.f;
        out[5*64*64 + 1 + g*64 + b] = (float)idx;
    }
}

__global__ void k_lred(float* out){
    __shared__ float s[320];
    int t = threadIdx.x;
    if (t < 320) s[t] = g_loss[t];
    __syncthreads();
    if (t==0){
        float a=0.f;
        for (int i=0;i<320;i++) a += s[i];
        out[5*64*64] = a;
    }
}

extern "C" void kernel_launch(void* const* d_in, const int* in_sizes, int n_in,
                              void* d_out, int out_size)
{
    const float* x        = (const float*)d_in[0];
    const float* embed_w  = (const float*)d_in[1];
    const float* embed_b  = (const float*)d_in[2];
    const float* sgcn_w1  = (const float*)d_in[3];
    const float* sgcn_b1  = (const float*)d_in[4];
    const float* tconv_w1 = (const float*)d_in[5];
    const float* tconv_b1 = (const float*)d_in[6];
    const float* bn_g1    = (const float*)d_in[7];
    const float* bn_b1    = (const float*)d_in[8];
    const float* res_w2   = (const float*)d_in[9];
    const float* res_b2   = (const float*)d_in[10];
    const float* resbn_g2 = (const float*)d_in[11];
    const float* resbn_b2 = (const float*)d_in[12];
    const float* sgcn_w2  = (const float*)d_in[13];
    const float* sgcn_b2  = (const float*)d_in[14];
    const float* tconv_w2 = (const float*)d_in[15];
    const float* tconv_b2 = (const float*)d_in[16];
    const float* bn_g2    = (const float*)d_in[17];
    const float* bn_b2    = (const float*)d_in[18];
    const float* res_w3   = (const float*)d_in[19];
    const float* res_b3   = (const float*)d_in[20];
    const float* resbn_g3 = (const float*)d_in[21];
    const float* resbn_b3 = (const float*)d_in[22];
    const float* sgcn_w3  = (const float*)d_in[23];
    const float* sgcn_b3  = (const float*)d_in[24];
    const float* tconv_w3 = (const float*)d_in[25];
    const float* tconv_b3 = (const float*)d_in[26];
    const float* bn_g3    = (const float*)d_in[27];
    const float* bn_b3    = (const float*)d_in[28];
    const float* codebooks= (const float*)d_in[29];
    float* out = (float*)d_out;

    void *vp;
    #define SYM(name, s) cudaGetSymbolAddress(&vp, s); float* name = (float*)vp;
    SYM(pH,  g_H)  SYM(pZ,  g_Z)  SYM(pY1, g_Y1) SYM(pY2, g_Y2) SYM(pY3, g_Y3)
    SYM(pSW1,g_sw1) SYM(pSB1,g_sb1) SYM(pSW2,g_sw2) SYM(pSB2,g_sb2)
    SYM(pSW3,g_sw3) SYM(pSB3,g_sb3) SYM(pRW2,g_rw2) SYM(pRW3,g_rw3)
    SYM(pC2, g_cst2) SYM(pC3, g_cst3)
    SYM(pTW1,g_tw1) SYM(pTW2,g_tw2) SYM(pTW3,g_tw3)
    #undef SYM

    const int NTILE = BT/TBL;          // 1024
    dim3 grid(NTILE, 5);

    auto swb = [](int cout){ return 8*(cout+1)*16; };   // sW4 bytes
    size_t sm_g1 = 96*64*4  + swb(64);
    size_t sm_g2 = 96*64*4  + swb(128);
    size_t sm_g3 = 96*128*4 + swb(64);
    size_t sm_t1 = ((TBL+2)*6*64)*4                     + swb(64);
    size_t sm_t2 = ((TBL+2)*6*128)*4                    + swb(128);
    size_t sm_t3 = (TBL*6*128)*4                        + swb(64);

    cudaFuncSetAttribute(k_gcn<128,64>,          cudaFuncAttributeMaxDynamicSharedMemorySize, (int)sm_g3);
    cudaFuncSetAttribute(k_tconv<128,128,64,1>,  cudaFuncAttributeMaxDynamicSharedMemorySize, (int)sm_t2);
    cudaFuncSetAttribute(k_tconv<64,64,128,1>,   cudaFuncAttributeMaxDynamicSharedMemorySize, (int)sm_t3);

    k_prep<<<64,256>>>(sgcn_w1, sgcn_b1, tconv_w1,
                       res_w2, res_b2, resbn_g2, resbn_b2, sgcn_w2, sgcn_b2, tconv_w2, tconv_b2,
                       res_w3, res_b3, resbn_g3, resbn_b3, sgcn_w3, sgcn_b3, tconv_w3, tconv_b3);

    k_embed<<<BT*25*64/256, 256>>>(x, embed_w, embed_b);

    // Layer 1 (COUT=64 -> 256 thr)
    k_gcn<64,64><<<grid,256,sm_g1>>>(pH, pZ, pSW1, pSB1);
    k_tconv<64,64,64,0><<<grid,256,sm_t1>>>(pZ, pH, pY1, pTW1, nullptr, tconv_b1, bn_g1, bn_b1);
    // Layer 2 (COUT=128 -> 512 thr)
    k_gcn<64,128><<<grid,512,sm_g2>>>(pY1, pZ, pSW2, pSB2);
    k_tconv<128,128,64,1><<<grid,512,sm_t2>>>(pZ, pY1, pY2, pTW2, pRW2, pC2, bn_g2, bn_b2);
    // Layer 3 (COUT=64 -> 256 thr)
    k_gcn<128,64><<<grid,256,sm_g3>>>(pY2, pZ, pSW3, pSB3);
    k_tconv<64,64,128,1><<<grid,256,sm_t3>>>(pZ, pY2, pY3, pTW3, pRW3, pC3, bn_g3, bn_b3);

    k_feat<<<dim3(5,64),256>>>();
    k_vq<<<dim3(5,64),128>>>(codebooks, out);
    k_lred<<<1,512>>>(out);
}

// round 5
// speedup vs baseline: 1.5803x; 1.5803x over previous
#include <cuda_runtime.h>

#define NB 64
#define NT 256
#define BT (NB*NT)
#define TBL 16
#define BNS 0.9999950000374997f

__constant__ int c_s2j[25] = {0,1,2,3,20, 4,5,6,7,21,22, 8,9,10,11,23,24, 12,13,14,15, 16,17,18,19};
__constant__ int c_gstart[5] = {0,5,11,17,21};
__constant__ int c_gn[5]     = {5,6,6,4,4};

__device__ float g_adj[5][6][6];
__device__ float g_H [BT*25*64];
__device__ float g_Z [BT*25*128];
__device__ float g_Y1[BT*25*64];
__device__ float g_Y2[BT*25*128];
__device__ float g_Y3[BT*25*64];
__device__ float g_feat[5*64*64];
__device__ float g_loss[5*64];
__device__ float g_sw1[5*64*64],  g_sb1[5*64];
__device__ float g_sw2[5*128*64], g_sb2[5*128];
__device__ float g_sw3[5*64*128], g_sb3[5*64];
__device__ float g_rw2[5*128*64], g_rw3[5*64*128];
__device__ float g_cst2[5*128],   g_cst3[5*64];
__device__ float g_tw1[5*3*64*64], g_tw2[5*3*128*128], g_tw3[5*3*64*64];

__global__ __launch_bounds__(256) void k_prep(
    const float* __restrict__ sw1, const float* __restrict__ sb1,
    const float* __restrict__ tw1,
    const float* __restrict__ rw2, const float* __restrict__ rb2,
    const float* __restrict__ rg2, const float* __restrict__ rbb2,
    const float* __restrict__ sw2, const float* __restrict__ sb2,
    const float* __restrict__ tw2, const float* __restrict__ tb2,
    const float* __restrict__ rw3, const float* __restrict__ rb3,
    const float* __restrict__ rg3, const float* __restrict__ rbb3,
    const float* __restrict__ sw3, const float* __restrict__ sb3,
    const float* __restrict__ tw3, const float* __restrict__ tb3)
{
    int gt  = blockIdx.x*blockDim.x + threadIdx.x;
    int NTH = gridDim.x*blockDim.x;
    for (int i=gt;i<5*64*64;i+=NTH){
        int g=i/4096, r=i%4096, o=r/64, c=r%64;
        const float* w = sw1 + g*192*64;
        g_sw1[i] = w[o*64+c] + w[(64+o)*64+c] + w[(128+o)*64+c];
    }
    for (int i=gt;i<5*128*64;i+=NTH){
        int g=i/8192, r=i%8192, o=r/64, c=r%64;
        const float* w = sw2 + g*384*64;
        g_sw2[i] = w[o*64+c] + w[(128+o)*64+c] + w[(256+o)*64+c];
    }
    for (int i=gt;i<5*64*128;i+=NTH){
        int g=i/8192, r=i%8192, o=r/128, c=r%128;
        const float* w = sw3 + g*192*128;
        g_sw3[i] = w[o*128+c] + w[(64+o)*128+c] + w[(128+o)*128+c];
    }
    for (int i=gt;i<5*128*64;i+=NTH){
        int g=i/8192, o=(i%8192)/64;
        g_rw2[i] = rw2[i] * rg2[g*128+o] * BNS;
    }
    for (int i=gt;i<5*64*128;i+=NTH){
        int g=i/8192, o=(i%8192)/128;
        g_rw3[i] = rw3[i] * rg3[g*64+o] * BNS;
    }
    for (int i=gt;i<5*3*64*64;i+=NTH){
        int c=i%64, o=(i/64)%64, kt=(i/4096)%3, g=i/12288;
        g_tw1[i] = tw1[((g*64+o)*64+c)*3+kt];
        g_tw3[i] = tw3[((g*64+o)*64+c)*3+kt];
    }
    for (int i=gt;i<5*3*128*128;i+=NTH){
        int c=i%128, o=(i/128)%128, kt=(i/16384)%3, g=i/49152;
        g_tw2[i] = tw2[((g*128+o)*128+c)*3+kt];
    }
    for (int i=gt;i<5*64;i+=NTH){
        int g=i/64, o=i%64;
        const float* s1 = sb1 + g*192;
        g_sb1[i]  = s1[o] + s1[64+o] + s1[128+o];
        const float* s3 = sb3 + g*192;
        g_sb3[i]  = s3[o] + s3[64+o] + s3[128+o];
        g_cst3[i] = tb3[i] + rb3[i]*rg3[i]*BNS + rbb3[i];
    }
    for (int i=gt;i<5*128;i+=NTH){
        int g=i/128, o=i%128;
        const float* s = sb2 + g*384;
        g_sb2[i]  = s[o] + s[128+o] + s[256+o];
        g_cst2[i] = tb2[i] + rb2[i]*rg2[i]*BNS + rbb2[i];
    }
    if (gt==0){
        double fa[25][25];
        for (int i=0;i<25;i++) for (int j=0;j<25;j++) fa[i][j]=0.0;
        const int E[24][2]={{3,2},{2,20},{20,1},{1,0},{20,4},{4,5},{5,6},{6,22},
                            {6,7},{7,21},{20,8},{8,9},{9,10},{10,24},{10,11},{11,23},
                            {0,12},{12,13},{13,14},{14,15},{0,16},{16,17},{17,18},{18,19}};
        for (int k=0;k<24;k++){
            int i=E[k][0]-1, j=E[k][1]-1;
            fa[i][j]=1.0; fa[j][i]=1.0;
        }
        for (int i=0;i<25;i++) fa[i][i]+=1.0;
        for (int i=0;i<25;i++){
            double d=0; for (int j=0;j<25;j++) d+=fa[i][j];
            if (d==0.0) d=1.0;
            for (int j=0;j<25;j++) fa[i][j]/=d;
        }
        for (int g=0;g<5;g++){
            int n=c_gn[g];
            int js[6]; for (int u=0;u<n;u++) js[u]=c_s2j[c_gstart[g]+u];
            double sa[6][6];
            for (int u=0;u<n;u++) for (int v=0;v<n;v++) sa[u][v]=fa[js[u]][js[v]];
            for (int u=0;u<n;u++) sa[u][u]+=1.0;
            double dg[6];
            for (int u=0;u<n;u++){ double d=0; for (int v=0;v<n;v++) d+=sa[u][v]; dg[u]=d; }
            for (int node=1;node<n;node++)
                if (dg[node]==1.0){ sa[0][node]=1.0; sa[node][0]=1.0; }
            for (int u=0;u<6;u++) for (int v=0;v<6;v++){
                float val=0.f;
                if (u<n && v<n){
                    double d=0; for (int w=0;w<n;w++) d+=sa[u][w];
                    if (d==0.0) d=1.0;
                    val=(float)(sa[u][v]/d);
                }
                g_adj[g][u][v]=val;
            }
        }
    }
}

__global__ __launch_bounds__(256) void k_embed(const float* __restrict__ x,
                                               const float* __restrict__ ew,
                                               const float* __restrict__ eb)
{
    int idx = blockIdx.x*256 + threadIdx.x;
    int c   = idx & 63;
    int row = idx >> 6;
    int s   = row % 25;
    int bt  = row / 25;
    int j   = c_s2j[s];
    const float* xp = x + (bt*25 + j)*3;
    g_H[idx] = eb[c] + xp[0]*ew[c*3+0] + xp[1]*ew[c*3+1] + xp[2]*ew[c*3+2];
}

// dot4 with ascending-k accumulation order (acc components = 4 strided columns)
__device__ __forceinline__ void dot4(float4& acc, float4 a, float4 w0, float4 w1, float4 w2, float4 w3){
    acc.x = fmaf(a.w,w0.w, fmaf(a.z,w0.z, fmaf(a.y,w0.y, fmaf(a.x,w0.x, acc.x))));
    acc.y = fmaf(a.w,w1.w, fmaf(a.z,w1.z, fmaf(a.y,w1.y, fmaf(a.x,w1.x, acc.y))));
    acc.z = fmaf(a.w,w2.w, fmaf(a.z,w2.z, fmaf(a.y,w2.y, fmaf(a.x,w2.x, acc.z))));
    acc.w = fmaf(a.w,w3.w, fmaf(a.z,w3.z, fmaf(a.y,w3.y, fmaf(a.x,w3.x, acc.w))));
}

// stage one 32-k chunk of W ([o][cin] row-major, stride CINW) into sW4[kk4][COUT+1];
// entry (kk4,o) = float4{W[o][k0+4*kk4 + 0..3]}
template<int COUT>
__device__ __forceinline__ void stageW(float4* sW4, const float* __restrict__ Wg,
                                       int CINW, int k0, int tid, int TH)
{
    for (int p = tid; p < COUT*8; p += TH){
        int o = p >> 3, kk4 = p & 7;
        const float* wp = Wg + o*CINW + k0 + kk4*4;
        sW4[kk4*(COUT+1) + o] = *(const float4*)wp;
    }
}

template<int CIN,int COUT>
__global__ __launch_bounds__((COUT/4)*16) void k_gcn(const float* __restrict__ Y,
                                                     float* __restrict__ Z,
                                                     const float* __restrict__ W,
                                                     const float* __restrict__ Bv)
{
    constexpr int CT = COUT/4;
    constexpr int TH = CT*16;
    extern __shared__ float sm[];
    float*  sA  = sm;                         // [96][CIN]
    float4* sW4 = (float4*)(sm + 96*CIN);     // [8][COUT+1]
    __shared__ float sAdj[6][6];

    const int g   = blockIdx.y;
    const int n   = c_gn[g];
    const int gs0 = c_gstart[g];
    const int bt0 = blockIdx.x * TBL;
    const int tid = threadIdx.x;
    if (tid < 36) sAdj[tid/6][tid%6] = g_adj[g][tid/6][tid%6];
    __syncthreads();

    constexpr int C4 = CIN/4;
    for (int p=tid; p<96*C4; p+=TH){
        int c4 = p % C4, r = p / C4, u = r % 6, t = r / 6;
        float4 acc = make_float4(0.f,0.f,0.f,0.f);
        if (u < n){
            const float4* yp = (const float4*)(Y + ((size_t)(bt0+t)*25 + gs0)*CIN) + c4;
            #pragma unroll
            for (int v=0; v<6; ++v)
                if (v < n){
                    float av = sAdj[u][v];
                    float4 yv = yp[(size_t)v*C4];
                    acc.x += av*yv.x; acc.y += av*yv.y; acc.z += av*yv.z; acc.w += av*yv.w;
                }
        }
        ((float4*)sA)[p] = acc;
    }

    const int ty = tid / CT, tx = tid % CT;
    float4 acc[6];
    {
        float4 b4;
        b4.x = Bv[g*COUT + tx];
        b4.y = Bv[g*COUT + tx + CT];
        b4.z = Bv[g*COUT + tx + 2*CT];
        b4.w = Bv[g*COUT + tx + 3*CT];
        #pragma unroll
        for (int i=0;i<6;++i) acc[i]=b4;
    }
    const float* Wg = W + g*COUT*CIN;

    for (int k0=0;k0<CIN;k0+=32){
        __syncthreads();
        stageW<COUT>(sW4, Wg, CIN, k0, tid, TH);
        __syncthreads();
        #pragma unroll
        for (int kk4=0;kk4<8;++kk4){
            const float4* wb = sW4 + kk4*(COUT+1) + tx;
            float4 w0=wb[0], w1=wb[CT], w2=wb[2*CT], w3=wb[3*CT];
            #pragma unroll
            for (int i=0;i<6;++i){
                float4 a = *(const float4*)(sA + (ty+16*i)*CIN + k0 + kk4*4);
                dot4(acc[i], a, w0,w1,w2,w3);
            }
        }
    }
    #pragma unroll
    for (int i=0;i<6;++i){
        int r = ty+16*i, t = r/6, u = r%6;
        if (u < n){
            float* zp = Z + ((size_t)(bt0+t)*25 + gs0+u)*COUT + tx;
            zp[0]    = acc[i].x;
            zp[CT]   = acc[i].y;
            zp[2*CT] = acc[i].z;
            zp[3*CT] = acc[i].w;
        }
    }
}

template<int CIN,int COUT,int CRES,int MODE>
__global__ __launch_bounds__((COUT/4)*16) void k_tconv(const float* __restrict__ Zin,
                                                       const float* __restrict__ Yres,
                                                       float* __restrict__ Yout,
                                                       const float* __restrict__ TWt,
                                                       const float* __restrict__ RW,
                                                       const float* __restrict__ CST,
                                                       const float* __restrict__ GS,
                                                       const float* __restrict__ BB)
{
    constexpr int CT = COUT/4;
    constexpr int TH = CT*16;
    constexpr int SZSZ = (TBL+2)*6*CIN;
    constexpr int SRSZ = TBL*6*CRES;
    constexpr int SBUF = (SZSZ > SRSZ ? SZSZ : SRSZ);
    extern __shared__ float sm[];
    float*  sB  = sm;
    float4* sW4 = (float4*)(sm + SBUF);       // [8][COUT+1]

    const int g   = blockIdx.y;
    const int n   = c_gn[g];
    const int gs0 = c_gstart[g];
    const int bt0 = blockIdx.x * TBL;
    const int t0  = bt0 & (NT-1);
    const int tid = threadIdx.x, ty = tid/CT, tx = tid%CT;

    constexpr int C4 = CIN/4;
    for (int p=tid; p<(TBL+2)*6*C4; p+=TH){
        int c4 = p % C4, r = p / C4, u = r % 6, hb = r / 6;
        int t = t0 + hb - 1;
        float4 v = make_float4(0.f,0.f,0.f,0.f);
        if (u < n && t >= 0 && t < NT)
            v = ((const float4*)(Zin + ((size_t)(bt0+hb-1)*25 + gs0+u)*CIN))[c4];
        ((float4*)sB)[p] = v;
    }

    float4 acc[6];
    #pragma unroll
    for (int i=0;i<6;++i) acc[i]=make_float4(0.f,0.f,0.f,0.f);

    const float* TWg = TWt + g*3*COUT*CIN;
    for (int kt=0;kt<3;++kt){
        for (int k0=0;k0<CIN;k0+=32){
            __syncthreads();
            stageW<COUT>(sW4, TWg + kt*COUT*CIN, CIN, k0, tid, TH);
            __syncthreads();
            #pragma unroll
            for (int kk4=0;kk4<8;++kk4){
                const float4* wb = sW4 + kk4*(COUT+1) + tx;
                float4 w0=wb[0], w1=wb[CT], w2=wb[2*CT], w3=wb[3*CT];
                #pragma unroll
                for (int i=0;i<6;++i){
                    float4 a = *(const float4*)(sB + (ty+16*i + 6*kt)*CIN + k0 + kk4*4);
                    dot4(acc[i], a, w0,w1,w2,w3);
                }
            }
        }
    }

    if (MODE==1){
        __syncthreads();
        constexpr int R4 = CRES/4;
        for (int p=tid; p<TBL*6*R4; p+=TH){
            int c4 = p % R4, r = p / R4, u = r % 6, t = r / 6;
            float4 v = make_float4(0.f,0.f,0.f,0.f);
            if (u < n)
                v = ((const float4*)(Yres + ((size_t)(bt0+t)*25 + gs0+u)*CRES))[c4];
            ((float4*)sB)[p] = v;
        }
        const float* RWg = RW + g*COUT*CRES;
        for (int k0=0;k0<CRES;k0+=32){
            __syncthreads();
            stageW<COUT>(sW4, RWg, CRES, k0, tid, TH);
            __syncthreads();
            #pragma unroll
            for (int kk4=0;kk4<8;++kk4){
                const float4* wb = sW4 + kk4*(COUT+1) + tx;
                float4 w0=wb[0], w1=wb[CT], w2=wb[2*CT], w3=wb[3*CT];
                #pragma unroll
                for (int i=0;i<6;++i){
                    float4 a = *(const float4*)(sB + (ty+16*i)*CRES + k0 + kk4*4);
                    dot4(acc[i], a, w0,w1,w2,w3);
                }
            }
        }
    }

    float4 cst, gs, bb;
    cst.x = CST[g*COUT+tx];      cst.y = CST[g*COUT+tx+CT];
    cst.z = CST[g*COUT+tx+2*CT]; cst.w = CST[g*COUT+tx+3*CT];
    gs.x  = GS [g*COUT+tx]*BNS;      gs.y  = GS [g*COUT+tx+CT]*BNS;
    gs.z  = GS [g*COUT+tx+2*CT]*BNS; gs.w  = GS [g*COUT+tx+3*CT]*BNS;
    bb.x  = BB [g*COUT+tx];      bb.y  = BB [g*COUT+tx+CT];
    bb.z  = BB [g*COUT+tx+2*CT]; bb.w  = BB [g*COUT+tx+3*CT];
    #pragma unroll
    for (int i=0;i<6;++i){
        int r = ty+16*i, t = r/6, u = r%6;
        if (u < n){
            size_t base = ((size_t)(bt0+t)*25 + gs0+u)*COUT + tx;
            float4 pre = acc[i];
            pre.x += cst.x; pre.y += cst.y; pre.z += cst.z; pre.w += cst.w;
            if (MODE==0){
                pre.x += Yres[base];
                pre.y += Yres[base+CT];
                pre.z += Yres[base+2*CT];
                pre.w += Yres[base+3*CT];
            }
            Yout[base]      = fmaxf(pre.x*gs.x + bb.x, 0.f);
            Yout[base+CT]   = fmaxf(pre.y*gs.y + bb.y, 0.f);
            Yout[base+2*CT] = fmaxf(pre.z*gs.z + bb.z, 0.f);
            Yout[base+3*CT] = fmaxf(pre.w*gs.w + bb.w, 0.f);
        }
    }
}

__global__ __launch_bounds__(256) void k_feat()
{
    int g = blockIdx.x, b = blockIdx.y;
    int tid = threadIdx.x;
    int o = tid & 63, part = tid >> 6;
    int n = c_gn[g], gs0 = c_gstart[g];
    float s = 0.f;
    int total = NT*n;
    for (int q=part; q<total; q+=4){
        int t = q / n, u = q % n;
        s += g_Y3[((size_t)(b*NT+t)*25 + gs0+u)*64 + o];
    }
    __shared__ float red[256];
    red[tid]=s; __syncthreads();
    if (part==0)
        g_feat[(g*64+b)*64 + o] = (red[o]+red[64+o]+red[128+o]+red[192+o]) / (float)(NT*n);
}

__global__ __launch_bounds__(128) void k_vq(const float* __restrict__ cb,
                                            float* __restrict__ out)
{
    int g = blockIdx.x, b = blockIdx.y;
    int k = threadIdx.x;
    const float* f   = g_feat + (g*64+b)*64;
    const float* ck  = cb + (g*128 + k)*64;
    float dot=0.f, scb=0.f;
    for (int o=0;o<64;++o){ dot += f[o]*ck[o]; scb += ck[o]*ck[o]; }
    float d = scb - 2.f*dot;

    __shared__ float ds[128];
    __shared__ int   sidx;
    ds[k]=d; __syncthreads();
    if (k==0){
        float best = ds[0]; int bi = 0;
        for (int kk=1;kk<128;++kk) if (ds[kk] < best){ best = ds[kk]; bi = kk; }
        sidx = bi;
    }
    __syncthreads();
    int idx = sidx;
    const float* cq = cb + (g*128 + idx)*64;
    __shared__ float dsq[64];
    if (k < 64){
        float q = cq[k];
        out[(g*64+b)*64 + k] = q;
        float dd = q - f[k];
        dsq[k] = dd*dd;
    }
    __syncthreads();
    if (k==0){
        float s=0.f;
        for (int o=0;o<64;++o) s += dsq[o];
        g_loss[g*64+b] = 1.25f * s / 4096.f;
        out[5*64*64 + 1 + g*64 + b] = (float)idx;
    }
}

__global__ void k_lred(float* out){
    __shared__ float s[320];
    int t = threadIdx.x;
    if (t < 320) s[t] = g_loss[t];
    __syncthreads();
    if (t==0){
        float a=0.f;
        for (int i=0;i<320;i++) a += s[i];
        out[5*64*64] = a;
    }
}

extern "C" void kernel_launch(void* const* d_in, const int* in_sizes, int n_in,
                              void* d_out, int out_size)
{
    const float* x        = (const float*)d_in[0];
    const float* embed_w  = (const float*)d_in[1];
    const float* embed_b  = (const float*)d_in[2];
    const float* sgcn_w1  = (const float*)d_in[3];
    const float* sgcn_b1  = (const float*)d_in[4];
    const float* tconv_w1 = (const float*)d_in[5];
    const float* tconv_b1 = (const float*)d_in[6];
    const float* bn_g1    = (const float*)d_in[7];
    const float* bn_b1    = (const float*)d_in[8];
    const float* res_w2   = (const float*)d_in[9];
    const float* res_b2   = (const float*)d_in[10];
    const float* resbn_g2 = (const float*)d_in[11];
    const float* resbn_b2 = (const float*)d_in[12];
    const float* sgcn_w2  = (const float*)d_in[13];
    const float* sgcn_b2  = (const float*)d_in[14];
    const float* tconv_w2 = (const float*)d_in[15];
    const float* tconv_b2 = (const float*)d_in[16];
    const float* bn_g2    = (const float*)d_in[17];
    const float* bn_b2    = (const float*)d_in[18];
    const float* res_w3   = (const float*)d_in[19];
    const float* res_b3   = (const float*)d_in[20];
    const float* resbn_g3 = (const float*)d_in[21];
    const float* resbn_b3 = (const float*)d_in[22];
    const float* sgcn_w3  = (const float*)d_in[23];
    const float* sgcn_b3  = (const float*)d_in[24];
    const float* tconv_w3 = (const float*)d_in[25];
    const float* tconv_b3 = (const float*)d_in[26];
    const float* bn_g3    = (const float*)d_in[27];
    const float* bn_b3    = (const float*)d_in[28];
    const float* codebooks= (const float*)d_in[29];
    float* out = (float*)d_out;

    void *vp;
    #define SYM(name, s) cudaGetSymbolAddress(&vp, s); float* name = (float*)vp;
    SYM(pH,  g_H)  SYM(pZ,  g_Z)  SYM(pY1, g_Y1) SYM(pY2, g_Y2) SYM(pY3, g_Y3)
    SYM(pSW1,g_sw1) SYM(pSB1,g_sb1) SYM(pSW2,g_sw2) SYM(pSB2,g_sb2)
    SYM(pSW3,g_sw3) SYM(pSB3,g_sb3) SYM(pRW2,g_rw2) SYM(pRW3,g_rw3)
    SYM(pC2, g_cst2) SYM(pC3, g_cst3)
    SYM(pTW1,g_tw1) SYM(pTW2,g_tw2) SYM(pTW3,g_tw3)
    #undef SYM

    const int NTILE = BT/TBL;          // 1024
    dim3 grid(NTILE, 5);

    auto swb = [](int cout){ return 8*(cout+1)*16; };   // sW4 bytes
    size_t sm_g1 = 96*64*4  + swb(64);
    size_t sm_g2 = 96*64*4  + swb(128);
    size_t sm_g3 = 96*128*4 + swb(64);
    size_t sm_t1 = ((TBL+2)*6*64)*4                     + swb(64);
    size_t sm_t2 = ((TBL+2)*6*128)*4                    + swb(128);
    size_t sm_t3 = (TBL*6*128)*4                        + swb(64);

    cudaFuncSetAttribute(k_gcn<128,64>,          cudaFuncAttributeMaxDynamicSharedMemorySize, (int)sm_g3);
    cudaFuncSetAttribute(k_tconv<128,128,64,1>,  cudaFuncAttributeMaxDynamicSharedMemorySize, (int)sm_t2);
    cudaFuncSetAttribute(k_tconv<64,64,128,1>,   cudaFuncAttributeMaxDynamicSharedMemorySize, (int)sm_t3);

    k_prep<<<64,256>>>(sgcn_w1, sgcn_b1, tconv_w1,
                       res_w2, res_b2, resbn_g2, resbn_b2, sgcn_w2, sgcn_b2, tconv_w2, tconv_b2,
                       res_w3, res_b3, resbn_g3, resbn_b3, sgcn_w3, sgcn_b3, tconv_w3, tconv_b3);

    k_embed<<<BT*25*64/256, 256>>>(x, embed_w, embed_b);

    k_gcn<64,64><<<grid,256,sm_g1>>>(pH, pZ, pSW1, pSB1);
    k_tconv<64,64,64,0><<<grid,256,sm_t1>>>(pZ, pH, pY1, pTW1, nullptr, tconv_b1, bn_g1, bn_b1);
    k_gcn<64,128><<<grid,512,sm_g2>>>(pY1, pZ, pSW2, pSB2);
    k_tconv<128,128,64,1><<<grid,512,sm_t2>>>(pZ, pY1, pY2, pTW2, pRW2, pC2, bn_g2, bn_b2);
    k_gcn<128,64><<<grid,256,sm_g3>>>(pY2, pZ, pSW3, pSB3);
    k_tconv<64,64,128,1><<<grid,256,sm_t3>>>(pZ, pY2, pY3, pTW3, pRW3, pC3, bn_g3, bn_b3);

    k_feat<<<dim3(5,64),256>>>();
    k_vq<<<dim3(5,64),128>>>(codebooks, out);
    k_lred<<<1,512>>>(out);
}

// round 6
// speedup vs baseline: 1.5901x; 1.0062x over previous
#include <cuda_runtime.h>

#define NB 64
#define NT 256
#define BT (NB*NT)
#define TBL 16
#define BNS 0.9999950000374997f

__constant__ int c_s2j[25] = {0,1,2,3,20, 4,5,6,7,21,22, 8,9,10,11,23,24, 12,13,14,15, 16,17,18,19};
__constant__ int c_gstart[5] = {0,5,11,17,21};
__constant__ int c_gn[5]     = {5,6,6,4,4};

__device__ float g_adj[5][6][6];
__device__ float g_H [BT*25*64];
__device__ float g_Z [BT*25*128];
__device__ float g_Y1[BT*25*64];
__device__ float g_Y2[BT*25*128];
__device__ float g_Y3[BT*25*64];
__device__ float g_feat[5*64*64];
__device__ float g_loss[5*64];
__device__ float g_sw1[5*64*64],  g_sb1[5*64];
__device__ float g_sw2[5*128*64], g_sb2[5*128];
__device__ float g_sw3[5*64*128], g_sb3[5*64];
__device__ float g_rw2[5*128*64], g_rw3[5*64*128];
__device__ float g_cst2[5*128],   g_cst3[5*64];
__device__ float g_tw1[5*3*64*64], g_tw2[5*3*128*128], g_tw3[5*3*64*64];

__global__ __launch_bounds__(256) void k_prep(
    const float* __restrict__ sw1, const float* __restrict__ sb1,
    const float* __restrict__ tw1,
    const float* __restrict__ rw2, const float* __restrict__ rb2,
    const float* __restrict__ rg2, const float* __restrict__ rbb2,
    const float* __restrict__ sw2, const float* __restrict__ sb2,
    const float* __restrict__ tw2, const float* __restrict__ tb2,
    const float* __restrict__ rw3, const float* __restrict__ rb3,
    const float* __restrict__ rg3, const float* __restrict__ rbb3,
    const float* __restrict__ sw3, const float* __restrict__ sb3,
    const float* __restrict__ tw3, const float* __restrict__ tb3)
{
    int gt  = blockIdx.x*blockDim.x + threadIdx.x;
    int NTH = gridDim.x*blockDim.x;
    for (int i=gt;i<5*64*64;i+=NTH){
        int g=i/4096, r=i%4096, o=r/64, c=r%64;
        const float* w = sw1 + g*192*64;
        g_sw1[i] = w[o*64+c] + w[(64+o)*64+c] + w[(128+o)*64+c];
    }
    for (int i=gt;i<5*128*64;i+=NTH){
        int g=i/8192, r=i%8192, o=r/64, c=r%64;
        const float* w = sw2 + g*384*64;
        g_sw2[i] = w[o*64+c] + w[(128+o)*64+c] + w[(256+o)*64+c];
    }
    for (int i=gt;i<5*64*128;i+=NTH){
        int g=i/8192, r=i%8192, o=r/128, c=r%128;
        const float* w = sw3 + g*192*128;
        g_sw3[i] = w[o*128+c] + w[(64+o)*128+c] + w[(128+o)*128+c];
    }
    for (int i=gt;i<5*128*64;i+=NTH){
        int g=i/8192, o=(i%8192)/64;
        g_rw2[i] = rw2[i] * rg2[g*128+o] * BNS;
    }
    for (int i=gt;i<5*64*128;i+=NTH){
        int g=i/8192, o=(i%8192)/128;
        g_rw3[i] = rw3[i] * rg3[g*64+o] * BNS;
    }
    for (int i=gt;i<5*3*64*64;i+=NTH){
        int c=i%64, o=(i/64)%64, kt=(i/4096)%3, g=i/12288;
        g_tw1[i] = tw1[((g*64+o)*64+c)*3+kt];
        g_tw3[i] = tw3[((g*64+o)*64+c)*3+kt];
    }
    for (int i=gt;i<5*3*128*128;i+=NTH){
        int c=i%128, o=(i/128)%128, kt=(i/16384)%3, g=i/49152;
        g_tw2[i] = tw2[((g*128+o)*128+c)*3+kt];
    }
    for (int i=gt;i<5*64;i+=NTH){
        int g=i/64, o=i%64;
        const float* s1 = sb1 + g*192;
        g_sb1[i]  = s1[o] + s1[64+o] + s1[128+o];
        const float* s3 = sb3 + g*192;
        g_sb3[i]  = s3[o] + s3[64+o] + s3[128+o];
        g_cst3[i] = tb3[i] + rb3[i]*rg3[i]*BNS + rbb3[i];
    }
    for (int i=gt;i<5*128;i+=NTH){
        int g=i/128, o=i%128;
        const float* s = sb2 + g*384;
        g_sb2[i]  = s[o] + s[128+o] + s[256+o];
        g_cst2[i] = tb2[i] + rb2[i]*rg2[i]*BNS + rbb2[i];
    }
    if (gt==0){
        double fa[25][25];
        for (int i=0;i<25;i++) for (int j=0;j<25;j++) fa[i][j]=0.0;
        const int E[24][2]={{3,2},{2,20},{20,1},{1,0},{20,4},{4,5},{5,6},{6,22},
                            {6,7},{7,21},{20,8},{8,9},{9,10},{10,24},{10,11},{11,23},
                            {0,12},{12,13},{13,14},{14,15},{0,16},{16,17},{17,18},{18,19}};
        for (int k=0;k<24;k++){
            int i=E[k][0]-1, j=E[k][1]-1;
            fa[i][j]=1.0; fa[j][i]=1.0;
        }
        for (int i=0;i<25;i++) fa[i][i]+=1.0;
        for (int i=0;i<25;i++){
            double d=0; for (int j=0;j<25;j++) d+=fa[i][j];
            if (d==0.0) d=1.0;
            for (int j=0;j<25;j++) fa[i][j]/=d;
        }
        for (int g=0;g<5;g++){
            int n=c_gn[g];
            int js[6]; for (int u=0;u<n;u++) js[u]=c_s2j[c_gstart[g]+u];
            double sa[6][6];
            for (int u=0;u<n;u++) for (int v=0;v<n;v++) sa[u][v]=fa[js[u]][js[v]];
            for (int u=0;u<n;u++) sa[u][u]+=1.0;
            double dg[6];
            for (int u=0;u<n;u++){ double d=0; for (int v=0;v<n;v++) d+=sa[u][v]; dg[u]=d; }
            for (int node=1;node<n;node++)
                if (dg[node]==1.0){ sa[0][node]=1.0; sa[node][0]=1.0; }
            for (int u=0;u<6;u++) for (int v=0;v<6;v++){
                float val=0.f;
                if (u<n && v<n){
                    double d=0; for (int w=0;w<n;w++) d+=sa[u][w];
                    if (d==0.0) d=1.0;
                    val=(float)(sa[u][v]/d);
                }
                g_adj[g][u][v]=val;
            }
        }
    }
}

__global__ __launch_bounds__(256) void k_embed(const float* __restrict__ x,
                                               const float* __restrict__ ew,
                                               const float* __restrict__ eb)
{
    int idx = blockIdx.x*256 + threadIdx.x;
    int c   = idx & 63;
    int row = idx >> 6;
    int s   = row % 25;
    int bt  = row / 25;
    int j   = c_s2j[s];
    const float* xp = x + (bt*25 + j)*3;
    g_H[idx] = eb[c] + xp[0]*ew[c*3+0] + xp[1]*ew[c*3+1] + xp[2]*ew[c*3+2];
}

// ascending-k dot: acc += a.k * w.k (k = x,y,z,w in order)
__device__ __forceinline__ float dot4s(float acc, float4 a, float4 w){
    return fmaf(a.w,w.w, fmaf(a.z,w.z, fmaf(a.y,w.y, fmaf(a.x,w.x, acc))));
}

// stage one 32-k chunk of W ([o][cin] row-major, stride CINW) into sW4[kk4][COUT+1];
// entry (kk4,o) = float4{W[o][k0+4*kk4 + 0..3]}
template<int COUT>
__device__ __forceinline__ void stageW(float4* sW4, const float* __restrict__ Wg,
                                       int CINW, int k0, int tid, int TH)
{
    for (int p = tid; p < COUT*8; p += TH){
        int o = p >> 3, kk4 = p & 7;
        const float* wp = Wg + o*CINW + k0 + kk4*4;
        sW4[kk4*(COUT+1) + o] = *(const float4*)wp;
    }
}

template<int CIN,int COUT>
__global__ __launch_bounds__((COUT/8)*16) void k_gcn(const float* __restrict__ Y,
                                                     float* __restrict__ Z,
                                                     const float* __restrict__ W,
                                                     const float* __restrict__ Bv)
{
    constexpr int CT = COUT/8;
    constexpr int TH = CT*16;
    constexpr int C4 = CIN/4;
    constexpr int PR = C4+1;                        // padded row stride (float4)
    extern __shared__ float sm[];
    float4* sA4 = (float4*)sm;                      // [96][PR]
    float4* sW4 = ((float4*)sm) + 96*PR;            // [8][COUT+1]
    __shared__ float sAdj[6][6];

    const int g   = blockIdx.y;
    const int n   = c_gn[g];
    const int gs0 = c_gstart[g];
    const int bt0 = blockIdx.x * TBL;
    const int tid = threadIdx.x;
    if (tid < 36) sAdj[tid/6][tid%6] = g_adj[g][tid/6][tid%6];
    __syncthreads();

    for (int p=tid; p<96*C4; p+=TH){
        int c4 = p % C4, r = p / C4, u = r % 6, t = r / 6;
        float4 acc = make_float4(0.f,0.f,0.f,0.f);
        if (u < n){
            const float4* yp = (const float4*)(Y + ((size_t)(bt0+t)*25 + gs0)*CIN) + c4;
            #pragma unroll
            for (int v=0; v<6; ++v)
                if (v < n){
                    float av = sAdj[u][v];
                    float4 yv = yp[(size_t)v*C4];
                    acc.x += av*yv.x; acc.y += av*yv.y; acc.z += av*yv.z; acc.w += av*yv.w;
                }
        }
        sA4[r*PR + c4] = acc;
    }

    const int ty = tid / CT, tx = tid % CT;
    float acc[6][8];
    #pragma unroll
    for (int j=0;j<8;++j){
        float b = Bv[g*COUT + tx + CT*j];
        #pragma unroll
        for (int i=0;i<6;++i) acc[i][j]=b;
    }
    const float* Wg = W + g*COUT*CIN;

    for (int k0=0;k0<CIN;k0+=32){
        __syncthreads();
        stageW<COUT>(sW4, Wg, CIN, k0, tid, TH);
        __syncthreads();
        #pragma unroll
        for (int kk4=0;kk4<8;++kk4){
            const float4* wb = sW4 + kk4*(COUT+1) + tx;
            float4 w[8];
            #pragma unroll
            for (int j=0;j<8;++j) w[j]=wb[CT*j];
            #pragma unroll
            for (int i=0;i<6;++i){
                float4 a = sA4[(ty+16*i)*PR + (k0>>2) + kk4];
                #pragma unroll
                for (int j=0;j<8;++j) acc[i][j] = dot4s(acc[i][j], a, w[j]);
            }
        }
    }
    #pragma unroll
    for (int i=0;i<6;++i){
        int r = ty+16*i, t = r/6, u = r%6;
        if (u < n){
            float* zp = Z + ((size_t)(bt0+t)*25 + gs0+u)*COUT + tx;
            #pragma unroll
            for (int j=0;j<8;++j) zp[CT*j] = acc[i][j];
        }
    }
}

template<int CIN,int COUT,int CRES,int MODE>
__global__ __launch_bounds__((COUT/8)*16) void k_tconv(const float* __restrict__ Zin,
                                                       const float* __restrict__ Yres,
                                                       float* __restrict__ Yout,
                                                       const float* __restrict__ TWt,
                                                       const float* __restrict__ RW,
                                                       const float* __restrict__ CST,
                                                       const float* __restrict__ GS,
                                                       const float* __restrict__ BB)
{
    constexpr int CT = COUT/8;
    constexpr int TH = CT*16;
    constexpr int C4 = CIN/4;
    constexpr int R4 = CRES/4;
    constexpr int PRZ = C4+1;
    constexpr int PRR = R4+1;
    constexpr int SZ4 = (TBL+2)*6*PRZ;              // Z tile float4s
    constexpr int SR4 = 96*PRR;                     // residual tile float4s
    constexpr int SBUF4 = (SZ4 > SR4 ? SZ4 : SR4);
    extern __shared__ float sm[];
    float4* sB4 = (float4*)sm;
    float4* sW4 = ((float4*)sm) + SBUF4;            // [8][COUT+1]

    const int g   = blockIdx.y;
    const int n   = c_gn[g];
    const int gs0 = c_gstart[g];
    const int bt0 = blockIdx.x * TBL;
    const int t0  = bt0 & (NT-1);
    const int tid = threadIdx.x, ty = tid/CT, tx = tid%CT;

    for (int p=tid; p<(TBL+2)*6*C4; p+=TH){
        int c4 = p % C4, r = p / C4, u = r % 6, hb = r / 6;
        int t = t0 + hb - 1;
        float4 v = make_float4(0.f,0.f,0.f,0.f);
        if (u < n && t >= 0 && t < NT)
            v = ((const float4*)(Zin + ((size_t)(bt0+hb-1)*25 + gs0+u)*CIN))[c4];
        sB4[r*PRZ + c4] = v;
    }

    float acc[6][8];
    #pragma unroll
    for (int i=0;i<6;++i)
        #pragma unroll
        for (int j=0;j<8;++j) acc[i][j]=0.f;

    const float* TWg = TWt + g*3*COUT*CIN;
    for (int kt=0;kt<3;++kt){
        for (int k0=0;k0<CIN;k0+=32){
            __syncthreads();
            stageW<COUT>(sW4, TWg + kt*COUT*CIN, CIN, k0, tid, TH);
            __syncthreads();
            #pragma unroll
            for (int kk4=0;kk4<8;++kk4){
                const float4* wb = sW4 + kk4*(COUT+1) + tx;
                float4 w[8];
                #pragma unroll
                for (int j=0;j<8;++j) w[j]=wb[CT*j];
                #pragma unroll
                for (int i=0;i<6;++i){
                    float4 a = sB4[(ty+16*i + 6*kt)*PRZ + (k0>>2) + kk4];
                    #pragma unroll
                    for (int j=0;j<8;++j) acc[i][j] = dot4s(acc[i][j], a, w[j]);
                }
            }
        }
    }

    if (MODE==1){
        __syncthreads();
        for (int p=tid; p<96*R4; p+=TH){
            int c4 = p % R4, r = p / R4, u = r % 6, t = r / 6;
            float4 v = make_float4(0.f,0.f,0.f,0.f);
            if (u < n)
                v = ((const float4*)(Yres + ((size_t)(bt0+t)*25 + gs0+u)*CRES))[c4];
            sB4[r*PRR + c4] = v;
        }
        const float* RWg = RW + g*COUT*CRES;
        for (int k0=0;k0<CRES;k0+=32){
            __syncthreads();
            stageW<COUT>(sW4, RWg, CRES, k0, tid, TH);
            __syncthreads();
            #pragma unroll
            for (int kk4=0;kk4<8;++kk4){
                const float4* wb = sW4 + kk4*(COUT+1) + tx;
                float4 w[8];
                #pragma unroll
                for (int j=0;j<8;++j) w[j]=wb[CT*j];
                #pragma unroll
                for (int i=0;i<6;++i){
                    float4 a = sB4[(ty+16*i)*PRR + (k0>>2) + kk4];
                    #pragma unroll
                    for (int j=0;j<8;++j) acc[i][j] = dot4s(acc[i][j], a, w[j]);
                }
            }
        }
    }

    float cst[8], gsv[8], bbv[8];
    #pragma unroll
    for (int j=0;j<8;++j){
        cst[j] = CST[g*COUT + tx + CT*j];
        gsv[j] = GS [g*COUT + tx + CT*j]*BNS;
        bbv[j] = BB [g*COUT + tx + CT*j];
    }
    #pragma unroll
    for (int i=0;i<6;++i){
        int r = ty+16*i, t = r/6, u = r%6;
        if (u < n){
            size_t base = ((size_t)(bt0+t)*25 + gs0+u)*COUT + tx;
            #pragma unroll
            for (int j=0;j<8;++j){
                float pre = acc[i][j] + cst[j];
                if (MODE==0) pre += Yres[base + CT*j];
                Yout[base + CT*j] = fmaxf(pre*gsv[j] + bbv[j], 0.f);
            }
        }
    }
}

__global__ __launch_bounds__(256) void k_feat()
{
    int g = blockIdx.x, b = blockIdx.y;
    int tid = threadIdx.x;
    int o = tid & 63, part = tid >> 6;
    int n = c_gn[g], gs0 = c_gstart[g];
    float s = 0.f;
    int total = NT*n;
    for (int q=part; q<total; q+=4){
        int t = q / n, u = q % n;
        s += g_Y3[((size_t)(b*NT+t)*25 + gs0+u)*64 + o];
    }
    __shared__ float red[256];
    red[tid]=s; __syncthreads();
    if (part==0)
        g_feat[(g*64+b)*64 + o] = (red[o]+red[64+o]+red[128+o]+red[192+o]) / (float)(NT*n);
}

__global__ __launch_bounds__(128) void k_vq(const float* __restrict__ cb,
                                            float* __restrict__ out)
{
    int g = blockIdx.x, b = blockIdx.y;
    int k = threadIdx.x;
    const float* f   = g_feat + (g*64+b)*64;
    const float* ck  = cb + (g*128 + k)*64;
    float dot=0.f, scb=0.f;
    for (int o=0;o<64;++o){ dot += f[o]*ck[o]; scb += ck[o]*ck[o]; }
    float d = scb - 2.f*dot;

    __shared__ float ds[128];
    __shared__ int   sidx;
    ds[k]=d; __syncthreads();
    if (k==0){
        float best = ds[0]; int bi = 0;
        for (int kk=1;kk<128;++kk) if (ds[kk] < best){ best = ds[kk]; bi = kk; }
        sidx = bi;
    }
    __syncthreads();
    int idx = sidx;
    const float* cq = cb + (g*128 + idx)*64;
    __shared__ float dsq[64];
    if (k < 64){
        float q = cq[k];
        out[(g*64+b)*64 + k] = q;
        float dd = q - f[k];
        dsq[k] = dd*dd;
    }
    __syncthreads();
    if (k==0){
        float s=0.f;
        for (int o=0;o<64;++o) s += dsq[o];
        g_loss[g*64+b] = 1.25f * s / 4096.f;
        out[5*64*64 + 1 + g*64 + b] = (float)idx;
    }
}

__global__ void k_lred(float* out){
    __shared__ float s[320];
    int t = threadIdx.x;
    if (t < 320) s[t] = g_loss[t];
    __syncthreads();
    if (t==0){
        float a=0.f;
        for (int i=0;i<320;i++) a += s[i];
        out[5*64*64] = a;
    }
}

extern "C" void kernel_launch(void* const* d_in, const int* in_sizes, int n_in,
                              void* d_out, int out_size)
{
    const float* x        = (const float*)d_in[0];
    const float* embed_w  = (const float*)d_in[1];
    const float* embed_b  = (const float*)d_in[2];
    const float* sgcn_w1  = (const float*)d_in[3];
    const float* sgcn_b1  = (const float*)d_in[4];
    const float* tconv_w1 = (const float*)d_in[5];
    const float* tconv_b1 = (const float*)d_in[6];
    const float* bn_g1    = (const float*)d_in[7];
    const float* bn_b1    = (const float*)d_in[8];
    const float* res_w2   = (const float*)d_in[9];
    const float* res_b2   = (const float*)d_in[10];
    const float* resbn_g2 = (const float*)d_in[11];
    const float* resbn_b2 = (const float*)d_in[12];
    const float* sgcn_w2  = (const float*)d_in[13];
    const float* sgcn_b2  = (const float*)d_in[14];
    const float* tconv_w2 = (const float*)d_in[15];
    const float* tconv_b2 = (const float*)d_in[16];
    const float* bn_g2    = (const float*)d_in[17];
    const float* bn_b2    = (const float*)d_in[18];
    const float* res_w3   = (const float*)d_in[19];
    const float* res_b3   = (const float*)d_in[20];
    const float* resbn_g3 = (const float*)d_in[21];
    const float* resbn_b3 = (const float*)d_in[22];
    const float* sgcn_w3  = (const float*)d_in[23];
    const float* sgcn_b3  = (const float*)d_in[24];
    const float* tconv_w3 = (const float*)d_in[25];
    const float* tconv_b3 = (const float*)d_in[26];
    const float* bn_g3    = (const float*)d_in[27];
    const float* bn_b3    = (const float*)d_in[28];
    const float* codebooks= (const float*)d_in[29];
    float* out = (float*)d_out;

    void *vp;
    #define SYM(name, s) cudaGetSymbolAddress(&vp, s); float* name = (float*)vp;
    SYM(pH,  g_H)  SYM(pZ,  g_Z)  SYM(pY1, g_Y1) SYM(pY2, g_Y2) SYM(pY3, g_Y3)
    SYM(pSW1,g_sw1) SYM(pSB1,g_sb1) SYM(pSW2,g_sw2) SYM(pSB2,g_sb2)
    SYM(pSW3,g_sw3) SYM(pSB3,g_sb3) SYM(pRW2,g_rw2) SYM(pRW3,g_rw3)
    SYM(pC2, g_cst2) SYM(pC3, g_cst3)
    SYM(pTW1,g_tw1) SYM(pTW2,g_tw2) SYM(pTW3,g_tw3)
    #undef SYM

    const int NTILE = BT/TBL;          // 1024
    dim3 grid(NTILE, 5);

    // shared sizes (bytes)
    auto swb = [](int cout){ return 8*(cout+1)*16; };
    size_t sm_g1 = 96*(64/4+1)*16  + swb(64);    // ~34.4 KB
    size_t sm_g2 = 96*(64/4+1)*16  + swb(128);   // ~42.6 KB
    size_t sm_g3 = 96*(128/4+1)*16 + swb(64);    // ~59.0 KB
    size_t sm_t1 = 108*(64/4+1)*16  + swb(64);   // ~37.7 KB
    size_t sm_t2 = 108*(128/4+1)*16 + swb(128);  // ~73.5 KB
    size_t sm_t3 = ((108*(64/4+1) > 96*(128/4+1)) ? 108*(64/4+1) : 96*(128/4+1))*16 + swb(64); // ~59.0 KB

    cudaFuncSetAttribute(k_gcn<128,64>,          cudaFuncAttributeMaxDynamicSharedMemorySize, (int)sm_g3);
    cudaFuncSetAttribute(k_tconv<128,128,64,1>,  cudaFuncAttributeMaxDynamicSharedMemorySize, (int)sm_t2);
    cudaFuncSetAttribute(k_tconv<64,64,128,1>,   cudaFuncAttributeMaxDynamicSharedMemorySize, (int)sm_t3);

    k_prep<<<64,256>>>(sgcn_w1, sgcn_b1, tconv_w1,
                       res_w2, res_b2, resbn_g2, resbn_b2, sgcn_w2, sgcn_b2, tconv_w2, tconv_b2,
                       res_w3, res_b3, resbn_g3, resbn_b3, sgcn_w3, sgcn_b3, tconv_w3, tconv_b3);

    k_embed<<<BT*25*64/256, 256>>>(x, embed_w, embed_b);

    k_gcn<64,64><<<grid,128,sm_g1>>>(pH, pZ, pSW1, pSB1);
    k_tconv<64,64,64,0><<<grid,128,sm_t1>>>(pZ, pH, pY1, pTW1, nullptr, tconv_b1, bn_g1, bn_b1);
    k_gcn<64,128><<<grid,256,sm_g2>>>(pY1, pZ, pSW2, pSB2);
    k_tconv<128,128,64,1><<<grid,256,sm_t2>>>(pZ, pY1, pY2, pTW2, pRW2, pC2, bn_g2, bn_b2);
    k_gcn<128,64><<<grid,128,sm_g3>>>(pY2, pZ, pSW3, pSB3);
    k_tconv<64,64,128,1><<<grid,128,sm_t3>>>(pZ, pY2, pY3, pTW3, pRW3, pC3, bn_g3, bn_b3);

    k_feat<<<dim3(5,64),256>>>();
    k_vq<<<dim3(5,64),128>>>(codebooks, out);
    k_lred<<<1,512>>>(out);
}